// round 12
// baseline (speedup 1.0000x reference)
#include <cuda_runtime.h>
#include <cuda_bf16.h>
#include <math.h>
#include <stdint.h>

// Problem constants
#define BB   16
#define SS   1024
#define EE   256
#define HH   256
#define G4H  1024
#define WT   256
#define MM   (BB * SS)

// ---------------------------------------------------------------------------
// Scratch
// ---------------------------------------------------------------------------
__device__ float g_pre_f[MM * G4H];
__device__ float g_pre_b[MM * G4H];
__device__ float g_pre_d[MM * G4H];
__device__ float g_hn[MM * HH];
__device__ float g_hb[MM * HH];
__device__ float g_dh[MM * HH];
__device__ float g_q [MM * WT];      // becomes A = tanh(b1+b2) after tanhq_kernel
__device__ float g_p [MM * WT];

// decide coordination (padded lines; zeroed by tanhq_kernel each replay)
__device__ float    g_decv[BB * 32];
__device__ int      g_deci[BB * 32];
__device__ int      g_tcur[BB * 32];
__device__ unsigned g_arr [BB * 32];
__device__ unsigned g_gen [BB * 32];

// ---------------------------------------------------------------------------
// PTX helpers
// ---------------------------------------------------------------------------
typedef unsigned long long u64t;
__device__ __forceinline__ u64t pack2(float lo, float hi) {
    u64t r; asm("mov.b64 %0, {%1,%2};" : "=l"(r) : "f"(lo), "f"(hi)); return r;
}
__device__ __forceinline__ void unpack2(float& lo, float& hi, u64t v) {
    asm("mov.b64 {%0,%1}, %2;" : "=f"(lo), "=f"(hi) : "l"(v));
}
__device__ __forceinline__ void fma2(u64t& d, u64t a, u64t b) {
    asm("fma.rn.f32x2 %0, %1, %2, %0;" : "+l"(d) : "l"(a), "l"(b));
}
__device__ __forceinline__ uint32_t smem_u32(const void* p) {
    uint32_t a;
    asm("{ .reg .u64 t; cvta.to.shared.u64 t, %1; cvt.u32.u64 %0, t; }"
        : "=r"(a) : "l"(p));
    return a;
}
__device__ __forceinline__ void st_cluster_f32(uint32_t laddr, uint32_t rank, float v) {
    uint32_t ra;
    asm volatile("mapa.shared::cluster.u32 %0, %1, %2;" : "=r"(ra) : "r"(laddr), "r"(rank));
    asm volatile("st.shared::cluster.f32 [%0], %1;" :: "r"(ra), "f"(v) : "memory");
}
__device__ __forceinline__ void mbar_init(uint32_t a, uint32_t cnt) {
    asm volatile("mbarrier.init.shared.b64 [%0], %1;" :: "r"(a), "r"(cnt) : "memory");
}
__device__ __forceinline__ void mbar_arrive_cluster(uint32_t laddr, uint32_t rank) {
    uint32_t ra;
    asm volatile("mapa.shared::cluster.u32 %0, %1, %2;" : "=r"(ra) : "r"(laddr), "r"(rank));
    asm volatile("mbarrier.arrive.release.cluster.shared::cluster.b64 _, [%0];"
                 :: "r"(ra) : "memory");
}
__device__ __forceinline__ void mbar_wait(uint32_t a, uint32_t parity) {
    asm volatile(
        "{\n\t.reg .pred P;\n"
        "WL%=:\n\t"
        "mbarrier.try_wait.parity.acquire.cluster.shared::cta.b64 P, [%0], %1, 0x989680;\n\t"
        "@P bra WD%=;\n\t"
        "bra WL%=;\n"
        "WD%=:\n\t}"
        :: "r"(a), "r"(parity) : "memory");
}
__device__ __forceinline__ unsigned ld_acquire_u32(const unsigned* p) {
    unsigned v;
    asm volatile("ld.acquire.gpu.global.u32 %0, [%1];" : "=r"(v) : "l"(p) : "memory");
    return v;
}

// fast activations (err ~1e-6; safe for downstream argmax)
__device__ __forceinline__ float sigm_fast(float x) {
    return __fdividef(1.0f, 1.0f + __expf(-x));
}
__device__ __forceinline__ float tanh_fast(float x) {
    return 1.0f - __fdividef(2.0f, __expf(2.0f * x) + 1.0f);
}

// ---------------------------------------------------------------------------
// Tiled fp32 GEMM with packed f32x2 FMA (unchanged, passing)
// ---------------------------------------------------------------------------
#define GBM 128
#define GBN 64
#define GBK 16

__global__ __launch_bounds__(256) void gemm_kernel(
    const float* __restrict__ A, const float* __restrict__ Bw,
    const float* __restrict__ bias, float* __restrict__ C,
    int N, int K, int shiftA, int accFlag)
{
    __shared__ __align__(16) float As[GBK][GBM + 4];
    __shared__ __align__(16) float Bs[GBK][GBN];
    const int bm  = blockIdx.y * GBM;
    const int bn  = blockIdx.x * GBN;
    const int tid = threadIdx.x;
    const int tx  = tid & 15;
    const int ty  = tid >> 4;

    u64t acc2[4][4];
#pragma unroll
    for (int i = 0; i < 4; i++)
#pragma unroll
        for (int j = 0; j < 4; j++) acc2[i][j] = pack2(0.f, 0.f);

    for (int k0 = 0; k0 < K; k0 += GBK) {
        {
            int kr = tid >> 4;
            int cq = tid & 15;
            float4 v = *(const float4*)(Bw + (size_t)(k0 + kr) * N + bn + cq * 4);
            *(float4*)(&Bs[kr][cq * 4]) = v;
        }
#pragma unroll
        for (int l = 0; l < 2; l++) {
            int f4 = tid + l * 256;
            int r  = f4 >> 2;
            int kq = f4 & 3;
            int gm = bm + r;
            float4 v;
            if (shiftA && ((gm & (SS - 1)) == 0)) {
                v = make_float4(0.f, 0.f, 0.f, 0.f);
            } else {
                v = *(const float4*)(A + (size_t)(gm - shiftA) * K + k0 + kq * 4);
            }
            As[kq * 4 + 0][r] = v.x;
            As[kq * 4 + 1][r] = v.y;
            As[kq * 4 + 2][r] = v.z;
            As[kq * 4 + 3][r] = v.w;
        }
        __syncthreads();
#pragma unroll
        for (int kk = 0; kk < GBK; kk++) {
            ulonglong2 A0 = *(const ulonglong2*)(&As[kk][ty * 8]);
            ulonglong2 A1 = *(const ulonglong2*)(&As[kk][ty * 8 + 4]);
            u64t ar[4] = {A0.x, A0.y, A1.x, A1.y};
            float4 bv = *(const float4*)(&Bs[kk][tx * 4]);
            u64t bd[4] = {pack2(bv.x, bv.x), pack2(bv.y, bv.y),
                          pack2(bv.z, bv.z), pack2(bv.w, bv.w)};
#pragma unroll
            for (int i = 0; i < 4; i++)
#pragma unroll
                for (int j = 0; j < 4; j++) fma2(acc2[i][j], ar[i], bd[j]);
        }
        __syncthreads();
    }

    float4 bias4 = make_float4(0.f, 0.f, 0.f, 0.f);
    if (!accFlag && bias) bias4 = *(const float4*)(bias + bn + tx * 4);
#pragma unroll
    for (int i = 0; i < 4; i++) {
        float r0[4], r1[4];
#pragma unroll
        for (int j = 0; j < 4; j++) unpack2(r0[j], r1[j], acc2[i][j]);
#pragma unroll
        for (int h = 0; h < 2; h++) {
            float* rv = h ? r1 : r0;
            int gm = bm + ty * 8 + i * 2 + h;
            float* crow = C + (size_t)gm * N + bn + tx * 4;
            float4 v = make_float4(rv[0], rv[1], rv[2], rv[3]);
            if (accFlag) {
                float4 old = *(const float4*)crow;
                v.x += old.x; v.y += old.y; v.z += old.z; v.w += old.w;
            } else {
                v.x += bias4.x; v.y += bias4.y; v.z += bias4.z; v.w += bias4.w;
            }
            *(float4*)crow = v;
        }
    }
}

// ---------------------------------------------------------------------------
// Persistent LSTM recurrence (VERBATIM from round 11 — passing)
// ---------------------------------------------------------------------------
__global__ __launch_bounds__(512, 1) __cluster_dims__(8, 1, 1)
void lstm_kernel(
    const float* __restrict__ pre,
    const float* __restrict__ Whh,
    float* __restrict__ hout,
    const float* __restrict__ cinit,
    int backward)
{
    const int batch = blockIdx.x >> 3;
    uint32_t rank;
    asm("mov.u32 %0, %%cluster_ctarank;" : "=r"(rank));
    const int slice = (int)rank;
    const int tid   = threadIdx.x;
    const int c     = tid & 127;
    const int kh    = tid >> 7;
    const int lid   = tid & 31;
    const int gcol  = ((c >> 5) << 8) + (slice << 5) + (c & 31);

    __shared__ __align__(16) float hs[2][HH];
    __shared__ float part[512];
    __shared__ __align__(8) unsigned long long mbar;

    u64t w2[32];
#pragma unroll
    for (int j = 0; j < 32; j++) {
        float wl = Whh[(size_t)(kh * 64 + 2 * j)     * G4H + gcol];
        float wh = Whh[(size_t)(kh * 64 + 2 * j + 1) * G4H + gcol];
        w2[j] = pack2(wl, wh);
    }

    float cst = 0.f;
    float pv[4];
    if (tid < 32) {
        if (cinit)
            cst = cinit[((size_t)batch * SS + (SS - 1)) * HH + (slice << 5) + lid];
        int t0 = backward ? (SS - 1) : 0;
        const float* pr = pre + ((size_t)batch * SS + t0) * G4H + (slice << 5) + lid;
#pragma unroll
        for (int g = 0; g < 4; g++) pv[g] = __ldcs(pr + g * HH);
    }
    if (tid < HH) hs[0][tid] = 0.f;

    const uint32_t hs_base = smem_u32(&hs[0][0]);
    const uint32_t mb_base = smem_u32(&mbar);
    if (tid == 0) mbar_init(mb_base, 8);
    __syncthreads();
    asm volatile("barrier.cluster.arrive.aligned;" ::: "memory");
    asm volatile("barrier.cluster.wait.aligned;"   ::: "memory");

    for (int s = 0; s < SS; s++) {
        const int t = backward ? (SS - 1 - s) : s;

        if (s > 0) mbar_wait(mb_base, (s - 1) & 1);

        const float2* hp = (const float2*)&hs[s & 1][kh * 64];
        u64t acc0 = pack2(0.f, 0.f), acc1 = acc0, acc2v = acc0, acc3 = acc0;
#pragma unroll
        for (int j = 0; j < 8; j++) {
            ulonglong2 hq0 = *(const ulonglong2*)(hp + j * 4);
            ulonglong2 hq1 = *(const ulonglong2*)(hp + j * 4 + 2);
            fma2(acc0, hq0.x, w2[j * 4 + 0]);
            fma2(acc1, hq0.y, w2[j * 4 + 1]);
            fma2(acc2v, hq1.x, w2[j * 4 + 2]);
            fma2(acc3, hq1.y, w2[j * 4 + 3]);
        }
        float l0, h0, l1, h1, l2, h2v, l3, h3;
        unpack2(l0, h0, acc0); unpack2(l1, h1, acc1);
        unpack2(l2, h2v, acc2v); unpack2(l3, h3, acc3);
        part[tid] = ((l0 + h0) + (l1 + h1)) + ((l2 + h2v) + (l3 + h3));
        __syncthreads();

        if (tid < 32) {
            float z[4];
#pragma unroll
            for (int g = 0; g < 4; g++) {
                int pc = g * 32 + lid;
                z[g] = (part[pc] + part[128 + pc])
                     + (part[256 + pc] + part[384 + pc]) + pv[g];
            }
            if (s + 1 < SS) {
                int tn = backward ? (SS - 2 - s) : (s + 1);
                const float* pr =
                    pre + ((size_t)batch * SS + tn) * G4H + (slice << 5) + lid;
#pragma unroll
                for (int g = 0; g < 4; g++) pv[g] = __ldcs(pr + g * HH);
            }
            float c2 = sigm_fast(z[1]) * cst + sigm_fast(z[0]) * tanh_fast(z[2]);
            cst = c2;
            float h2 = sigm_fast(z[3]) * tanh_fast(c2);
            hout[((size_t)batch * SS + t) * HH + (slice << 5) + lid] = h2;
            if (s + 1 < SS) {
                uint32_t laddr = hs_base +
                    (uint32_t)((((s + 1) & 1) * HH + (slice << 5) + lid) * 4);
#pragma unroll
                for (uint32_t r = 0; r < 8; r++) st_cluster_f32(laddr, r, h2);
                __syncwarp();
                if (lid < 8)
                    mbar_arrive_cluster(mb_base, (uint32_t)lid);
            }
        }
    }
}

// ---------------------------------------------------------------------------
// D1: A = tanh(q) in place (16M elems); zero out; zero decide counters.
// ---------------------------------------------------------------------------
__global__ __launch_bounds__(256) void tanhq_kernel(float* __restrict__ q,
                                                    float* __restrict__ out)
{
    int i = blockIdx.x * 256 + threadIdx.x;
    int stride = gridDim.x * 256;
    for (int k = i; k < MM * WT; k += stride)
        q[k] = tanh_fast(q[k]);
    for (int k = i; k < SS * BB; k += stride)
        out[k] = 0.f;
    if (i < BB * 32) { g_arr[i] = 0u; g_gen[i] = 0u; }
}

// ---------------------------------------------------------------------------
// D2: pointer decisions, 8 blocks per batch (128 persistent blocks).
// A = tanh(a) precomputed; per element tanh(a+c) = (A+C)/(1+AC): 1 MUFU.
// Row-interleaved split: block c, thread tid -> row j = t + c + 8*tid.
// Per-iteration combine via single-publisher fence+counter (sound).
// ---------------------------------------------------------------------------
__global__ __launch_bounds__(512, 1) void decide2_kernel(
    const float* __restrict__ Aq,   // [B,S,WT] tanh'd
    const float* __restrict__ pm,   // [B,S,WT]
    const float* __restrict__ vt1,  // [WT]
    float* __restrict__ out)        // [S,B]
{
    const int b   = blockIdx.x >> 3;
    const int cb  = blockIdx.x & 7;
    const int tid = threadIdx.x;
    const int wid = tid >> 5;
    const int lane = tid & 31;

    __shared__ float Cs[WT];
    __shared__ float v1[WT];
    __shared__ float wv[16];
    __shared__ int   wi_[16];
    __shared__ int   t_sh;

    if (tid < WT) v1[tid] = vt1[tid];

    int t = 0;
    for (int it = 1;; it++) {
        if (tid < WT) Cs[tid] = tanh_fast(__ldg(&pm[((size_t)b * SS + t) * WT + tid]));
        __syncthreads();

        float bv = -1e30f;
        int   bj = SS;
        int   j  = t + cb + 8 * tid;     // tid<128 covers the whole suffix
        if (tid < 128 && j < SS) {
            const float* qr = Aq + ((size_t)b * SS + j) * WT;
            float sacc = 0.f;
#pragma unroll 4
            for (int w = 0; w < WT; w += 4) {
                float4 aq = *(const float4*)(qr + w);
                float4 cq = *(const float4*)(&Cs[w]);
                float4 vq = *(const float4*)(&v1[w]);
                sacc += vq.x * __fdividef(aq.x + cq.x, fmaf(aq.x, cq.x, 1.f));
                sacc += vq.y * __fdividef(aq.y + cq.y, fmaf(aq.y, cq.y, 1.f));
                sacc += vq.z * __fdividef(aq.z + cq.z, fmaf(aq.z, cq.z, 1.f));
                sacc += vq.w * __fdividef(aq.w + cq.w, fmaf(aq.w, cq.w, 1.f));
            }
            bv = sacc; bj = j;
        }
        // warp argmax (first-index tie-break; idx increases with tid)
#pragma unroll
        for (int off = 16; off > 0; off >>= 1) {
            float v2 = __shfl_down_sync(0xFFFFFFFFu, bv, off);
            int   i2 = __shfl_down_sync(0xFFFFFFFFu, bj, off);
            if (v2 > bv || (v2 == bv && i2 < bj)) { bv = v2; bj = i2; }
        }
        if (lane == 0) { wv[wid] = bv; wi_[wid] = bj; }
        __syncthreads();

        if (tid == 0) {
            float best = wv[0]; int bi = wi_[0];
#pragma unroll
            for (int k = 1; k < 16; k++)
                if (wv[k] > best || (wv[k] == best && wi_[k] < bi)) {
                    best = wv[k]; bi = wi_[k];
                }
            g_decv[b * 32 + cb] = best;
            g_deci[b * 32 + cb] = bi;
            __threadfence();
            atomicAdd(&g_arr[b * 32], 1u);
            if (cb == 0) {
                while (ld_acquire_u32(&g_arr[b * 32]) < 8u * (unsigned)it) { }
                float fb = g_decv[b * 32]; int fi = g_deci[b * 32];
#pragma unroll
                for (int k = 1; k < 8; k++) {
                    float v2 = g_decv[b * 32 + k]; int i2 = g_deci[b * 32 + k];
                    if (v2 > fb || (v2 == fb && i2 < fi)) { fb = v2; fi = i2; }
                }
                out[fi * BB + b] = 1.0f;
                g_tcur[b * 32] = (fi <= t) ? -1 : fi;
                __threadfence();
                atomicAdd(&g_gen[b * 32], 1u);
            }
            while (ld_acquire_u32(&g_gen[b * 32]) < (unsigned)it) { }
            t_sh = g_tcur[b * 32];
        }
        __syncthreads();
        t = t_sh;
        if (t < 0) break;
        __syncthreads();   // protect Cs rewrite vs slow readers
    }
}

// ---------------------------------------------------------------------------
// Launch (lstm fwd kept as my 4th launch for the ncu capture slot)
// ---------------------------------------------------------------------------
extern "C" void kernel_launch(void* const* d_in, const int* in_sizes, int n_in,
                              void* d_out, int out_size) {
    const float* x        = (const float*)d_in[0];
    const float* eWih_f   = (const float*)d_in[1];
    const float* eWhh_f   = (const float*)d_in[2];
    const float* eb_f     = (const float*)d_in[3];
    const float* eWih_b   = (const float*)d_in[4];
    const float* eWhh_b   = (const float*)d_in[5];
    const float* eb_b     = (const float*)d_in[6];
    const float* dWih     = (const float*)d_in[7];
    const float* dWhh     = (const float*)d_in[8];
    const float* db       = (const float*)d_in[9];
    const float* W1       = (const float*)d_in[10];
    const float* W2       = (const float*)d_in[11];
    const float* W3       = (const float*)d_in[12];
    const float* W4       = (const float*)d_in[13];
    const float* vt1      = (const float*)d_in[14];
    float*       out      = (float*)d_out;

    float *pre_f, *pre_b, *pre_d, *hn, *hb, *dh, *q, *p;
    cudaGetSymbolAddress((void**)&pre_f, g_pre_f);
    cudaGetSymbolAddress((void**)&pre_b, g_pre_b);
    cudaGetSymbolAddress((void**)&pre_d, g_pre_d);
    cudaGetSymbolAddress((void**)&hn,    g_hn);
    cudaGetSymbolAddress((void**)&hb,    g_hb);
    cudaGetSymbolAddress((void**)&dh,    g_dh);
    cudaGetSymbolAddress((void**)&q,     g_q);
    cudaGetSymbolAddress((void**)&p,     g_p);

    dim3 thr(256);
    dim3 gridBig(G4H / GBN, MM / GBM);   // N=1024
    dim3 gridSml(WT / GBN, MM / GBM);    // N=256

    // 1-3
    gemm_kernel<<<gridBig, thr>>>(x, eWih_f, eb_f, pre_f, G4H, EE, 0, 0);
    gemm_kernel<<<gridBig, thr>>>(x, eWih_b, eb_b, pre_b, G4H, EE, 0, 0);
    gemm_kernel<<<gridSml, thr>>>(x, W3, nullptr, p, WT, EE, 0, 0);

    // 4: forward encoder  <-- ncu capture slot
    lstm_kernel<<<128, 512>>>(pre_f, eWhh_f, hn, nullptr, 0);

    // 5-6
    lstm_kernel<<<128, 512>>>(pre_b, eWhh_b, hb, nullptr, 1);
    gemm_kernel<<<gridBig, thr>>>(x, dWih,   db,   pre_d, G4H, EE, 1, 0);

    // 7-10
    gemm_kernel<<<gridSml, thr>>>(x, W2, nullptr, q, WT, EE, 0, 0);
    gemm_kernel<<<gridBig, thr>>>(hn, dWih + (size_t)EE * G4H, nullptr, pre_d, G4H, HH, 1, 1);
    gemm_kernel<<<gridSml, thr>>>(hn, W1, nullptr, q, WT, HH, 0, 1);
    gemm_kernel<<<gridSml, thr>>>(hb, W1 + (size_t)HH * WT, nullptr, q, WT, HH, 0, 1);

    // 11-12
    lstm_kernel<<<128, 512>>>(pre_d, dWhh, dh, hn, 0);
    gemm_kernel<<<gridSml, thr>>>(dh, W4, nullptr, p, WT, HH, 0, 1);

    // 13: A = tanh(q), zero out + counters
    tanhq_kernel<<<2048, 256>>>(q, out);

    // 14: decisions (8 blocks/batch)
    decide2_kernel<<<BB * 8, 512>>>(q, p, vt1, out);
}